// round 13
// baseline (speedup 1.0000x reference)
#include <cuda_runtime.h>
#include <cuda_fp16.h>
#include <math.h>

#define NNODES 50000
#define DIM    128
#define NCLS   40
#define EMAX   600000
#define SCAN_B 1024
#define NSB    ((NNODES + SCAN_B - 1) / SCAN_B)

// ---------------- device scratch ------------------------------------------
__device__ unsigned g_epoch = 0;
__device__ int     g_cnt[NNODES];
__device__ int     g_cur[NNODES];
__device__ int     g_off[NNODES + 1];
__device__ unsigned long long g_state[NSB];
__device__ int2    g_csr2[EMAX];                 // {src, half2(dinv[src]) bits}
__device__ float   g_dinv[NNODES];
__device__ __half2 g_w1h[DIM * DIM / 2];
__device__ __half2 g_w2h[DIM * DIM / 2];
__device__ __half2 g_hs2[NNODES * (DIM / 2)];    // RAW features h, fp16
__device__ __half2 g_ag2[NNODES * (DIM / 2)];    // layer-1 aggregation, fp16

__device__ __forceinline__ int detect64_block(const int* ei) {
    __shared__ int s_is64;
    if (threadIdx.x == 0) {
        int nz = 0;
        #pragma unroll
        for (int j = 0; j < 16; j++) nz += (ei[2 * j + 1] != 0);
        s_is64 = (nz == 0) ? 1 : 0;
    }
    __syncthreads();
    return s_is64;
}

// ---------------- cnt (+ W->fp16, + epoch bump) ---------------------------
__global__ void k_cnt(const void* ei, long long E,
                      const float* __restrict__ W1, const float* __restrict__ W2) {
    const int is64 = detect64_block((const int*)ei);
    int gid = blockIdx.x * 256 + threadIdx.x;
    if (gid == 0) atomicAdd(&g_epoch, 1u);
    if (gid < DIM * DIM / 2) {
        float2 a = *(const float2*)&W1[2 * gid];
        float2 b = *(const float2*)&W2[2 * gid];
        g_w1h[gid] = __floats2half2_rn(a.x, a.y);
        g_w2h[gid] = __floats2half2_rn(b.x, b.y);
    }
    long long base = (long long)gid * 2;
    if (base >= E) return;
    int d0, d1; bool two = (base + 1 < E);
    if (is64) {
        const long long* pd = (const long long*)ei + E;
        if (two) { longlong2 v = *(const longlong2*)&pd[base]; d0 = (int)v.x; d1 = (int)v.y; }
        else d0 = (int)pd[base];
    } else {
        const int* pd = (const int*)ei + (size_t)E;
        if (two) { int2 v = *(const int2*)&pd[base]; d0 = v.x; d1 = v.y; }
        else d0 = pd[base];
    }
    atomicAdd(&g_cnt[d0], 1);
    if (two) atomicAdd(&g_cnt[d1], 1);
}

// ------- one-pass epoch-tagged lookback scan (+dinv, +cursors, cnt reset) --
__global__ void __launch_bounds__(SCAN_B) k_scan() {
    __shared__ int wsum[32];
    __shared__ int s_run;
    const int tid = threadIdx.x, lane = tid & 31, wid = tid >> 5;
    const int bid = blockIdx.x;
    const int i = bid * SCAN_B + tid;

    const unsigned e = g_epoch;
    const unsigned long long flagP = (unsigned long long)(2u * e + 1u) << 32;
    const unsigned long long flagF = (unsigned long long)(2u * e + 2u) << 32;

    int v = (i < NNODES) ? g_cnt[i] : 0;
    if (i < NNODES) {
        g_dinv[i] = rsqrtf((float)(v + 1));
        g_cnt[i] = 0;
    }

    int incl = v;
    #pragma unroll
    for (int s = 1; s < 32; s <<= 1) {
        int t = __shfl_up_sync(0xffffffffu, incl, s);
        if (lane >= s) incl += t;
    }
    if (lane == 31) wsum[wid] = incl;
    __syncthreads();
    if (wid == 0) {
        int w = wsum[lane];
        int wi = w;
        #pragma unroll
        for (int s = 1; s < 32; s <<= 1) {
            int t = __shfl_up_sync(0xffffffffu, wi, s);
            if (lane >= s) wi += t;
        }
        wsum[lane] = wi - w;
    }
    __syncthreads();
    int excl = incl - v + wsum[wid];

    if (tid == SCAN_B - 1) {
        int total = excl + v;
        long long run = 0;
        if (bid == 0) {
            atomicExch(&g_state[0], flagF | (unsigned)total);
        } else {
            atomicExch(&g_state[bid], flagP | (unsigned)total);
            int p = bid - 1;
            while (true) {
                unsigned long long st = atomicAdd(&g_state[p], 0ULL);
                unsigned long long f = st & 0xFFFFFFFF00000000ULL;
                if (f == flagF) { run += (int)(unsigned)st; break; }
                if (f == flagP) { run += (int)(unsigned)st; --p; continue; }
                __nanosleep(20);
            }
            atomicExch(&g_state[bid], flagF | (unsigned)(run + total));
        }
        s_run = (int)run;
        if (bid == NSB - 1) g_off[NNODES] = (int)run + total;
    }
    __syncthreads();
    if (i < NNODES) {
        int o = excl + s_run;
        g_off[i] = o;
        g_cur[i] = o;
    }
}

// ---------------- fill body: csr payload carries half2(dinv[src]) ---------
__device__ __forceinline__ void fill_body(int bx, const void* ei, long long E,
                                          int is64) {
    long long base = ((long long)bx * 256 + threadIdx.x) * 2;
    if (base >= E) return;
    int s0, s1, d0, d1; bool two = (base + 1 < E);
    if (is64) {
        const long long* ps = (const long long*)ei;
        const long long* pd = ps + E;
        if (two) {
            longlong2 vs = *(const longlong2*)&ps[base];
            longlong2 vd = *(const longlong2*)&pd[base];
            s0 = (int)vs.x; s1 = (int)vs.y; d0 = (int)vd.x; d1 = (int)vd.y;
        } else { s0 = (int)ps[base]; d0 = (int)pd[base]; }
    } else {
        const int* ps = (const int*)ei;
        const int* pd = ps + (size_t)E;
        if (two) {
            int2 vs = *(const int2*)&ps[base];
            int2 vd = *(const int2*)&pd[base];
            s0 = vs.x; s1 = vs.y; d0 = vd.x; d1 = vd.y;
        } else { s0 = ps[base]; d0 = pd[base]; }
    }
    float f0 = __ldg(&g_dinv[s0]);
    float f1 = two ? __ldg(&g_dinv[s1]) : 0.f;
    __half2 h0 = __floats2half2_rn(f0, f0);
    __half2 h1 = __floats2half2_rn(f1, f1);
    int p0 = atomicAdd(&g_cur[d0], 1);
    int p1 = two ? atomicAdd(&g_cur[d1], 1) : 0;
    g_csr2[p0] = make_int2(s0, *(int*)&h0);
    if (two) g_csr2[p1] = make_int2(s1, *(int*)&h1);
}

// ---------------- tensor-core GEMM body (swizzled, 64-row tile) -----------
#define A_BYTES (64 * 256)
#define GEMM_SMEM (A_BYTES + 128 * 256)

__device__ __forceinline__ unsigned sw_off(int r, int chunk) {
    return (unsigned)(r * 256 + ((chunk ^ (r & 7)) << 4));
}

__device__ void gemm_body(int bx, const float* __restrict__ x,
                          const __half2* __restrict__ Wh,
                          const float* __restrict__ bias,
                          int mode, char* smc) {
    char* Asb = smc;
    char* Wsb = smc + A_BYTES;
    const int tid = threadIdx.x;
    const int r0  = bx * 64;

    #pragma unroll
    for (int j = 0; j < 8; j++) {
        int chunk = tid + j * 256;
        int c  = chunk >> 4;
        int k8 = chunk & 15;
        uint4 u = *(const uint4*)((const char*)Wh + (size_t)chunk * 16);
        *(uint4*)(Wsb + sw_off(c, k8)) = u;
    }
    #pragma unroll
    for (int j = 0; j < 8; j++) {
        int flat = (tid + j * 256) * 4;
        int rl = flat >> 7, k = flat & 127;
        int r = r0 + rl;
        float4 v = make_float4(0.f, 0.f, 0.f, 0.f);
        if (r < NNODES) {
            if (mode == 0) {
                v = *(const float4*)&x[(size_t)r * DIM + k];
            } else {
                uint2 u = *(const uint2*)&g_ag2[(size_t)r * 64 + (k >> 1)];
                float2 a0 = __half22float2(*(const __half2*)&u.x);
                float2 a1 = __half22float2(*(const __half2*)&u.y);
                float4 b = *(const float4*)&bias[k];
                float di = g_dinv[r];
                v.x = fmaxf(fmaf(a0.x, di, b.x), 0.f);
                v.y = fmaxf(fmaf(a0.y, di, b.y), 0.f);
                v.z = fmaxf(fmaf(a1.x, di, b.z), 0.f);
                v.w = fmaxf(fmaf(a1.y, di, b.w), 0.f);
            }
        }
        uint2 u;
        *(__half2*)&u.x = __floats2half2_rn(v.x, v.y);
        *(__half2*)&u.y = __floats2half2_rn(v.z, v.w);
        *(uint2*)(Asb + sw_off(rl, k >> 3) + ((k & 7) << 1)) = u;
    }
    __syncthreads();

    const int warp = tid >> 5, lane = tid & 31;
    const int m0 = (warp >> 1) * 16;
    const int n0 = (warp & 1) * 64;
    const int gid = lane >> 2, tig = lane & 3;

    float acc[8][4];
    #pragma unroll
    for (int t = 0; t < 8; t++)
        #pragma unroll
        for (int q = 0; q < 4; q++) acc[t][q] = 0.f;

    unsigned aSm = (unsigned)__cvta_generic_to_shared(Asb);
    unsigned wSm = (unsigned)__cvta_generic_to_shared(Wsb);
    const int aRow = m0 + (lane & 15);
    const int aChA = (lane & 16) ? 1 : 0;
    const int bRow = ((lane & 16) ? 8 : 0) + (lane & 7);
    const int bChA = (lane & 8) ? 1 : 0;

    #pragma unroll
    for (int ks = 0; ks < 8; ks++) {
        unsigned a0, a1, a2, a3;
        unsigned aAddr = aSm + sw_off(aRow, 2 * ks + aChA);
        asm volatile("ldmatrix.sync.aligned.m8n8.x4.shared.b16 {%0,%1,%2,%3},[%4];"
                     : "=r"(a0), "=r"(a1), "=r"(a2), "=r"(a3) : "r"(aAddr));
        #pragma unroll
        for (int tp = 0; tp < 4; tp++) {
            unsigned b0, b1, b2, b3;
            unsigned bAddr = wSm + sw_off(n0 + 16 * tp + bRow, 2 * ks + bChA);
            asm volatile("ldmatrix.sync.aligned.m8n8.x4.shared.b16 {%0,%1,%2,%3},[%4];"
                         : "=r"(b0), "=r"(b1), "=r"(b2), "=r"(b3) : "r"(bAddr));
            asm volatile("mma.sync.aligned.m16n8k16.row.col.f32.f16.f16.f32 "
                         "{%0,%1,%2,%3},{%4,%5,%6,%7},{%8,%9},{%0,%1,%2,%3};"
                         : "+f"(acc[2 * tp][0]), "+f"(acc[2 * tp][1]),
                           "+f"(acc[2 * tp][2]), "+f"(acc[2 * tp][3])
                         : "r"(a0), "r"(a1), "r"(a2), "r"(a3), "r"(b0), "r"(b1));
            asm volatile("mma.sync.aligned.m16n8k16.row.col.f32.f16.f16.f32 "
                         "{%0,%1,%2,%3},{%4,%5,%6,%7},{%8,%9},{%0,%1,%2,%3};"
                         : "+f"(acc[2 * tp + 1][0]), "+f"(acc[2 * tp + 1][1]),
                           "+f"(acc[2 * tp + 1][2]), "+f"(acc[2 * tp + 1][3])
                         : "r"(a0), "r"(a1), "r"(a2), "r"(a3), "r"(b2), "r"(b3));
        }
    }

    const int r1 = r0 + m0 + gid;
    const int r2 = r1 + 8;
    #pragma unroll
    for (int t = 0; t < 8; t++) {
        int ci = (n0 >> 1) + 4 * t + tig;
        if (r1 < NNODES)
            g_hs2[(size_t)r1 * 64 + ci] = __floats2half2_rn(acc[t][0], acc[t][1]);
        if (r2 < NNODES)
            g_hs2[(size_t)r2 * 64 + ci] = __floats2half2_rn(acc[t][2], acc[t][3]);
    }
}

// fused: first nGemm blocks do gemm1 (long pole first), rest do CSR fill
__global__ void __launch_bounds__(256, 4) k_gemm_fill(const float* __restrict__ x,
                                                      const __half2* __restrict__ Wh,
                                                      const void* ei, long long E,
                                                      int nGemm) {
    extern __shared__ char smc[];
    if (blockIdx.x < nGemm) {
        gemm_body(blockIdx.x, x, Wh, nullptr, 0, smc);
    } else {
        const int is64 = detect64_block((const int*)ei);
        fill_body(blockIdx.x - nGemm, ei, E, is64);
    }
}

__global__ void __launch_bounds__(256, 4) k_gemm(const float* __restrict__ x,
                                                 const __half2* __restrict__ Wh,
                                                 const float* __restrict__ bias,
                                                 int mode) {
    extern __shared__ char smc[];
    gemm_body(blockIdx.x, x, Wh, bias, mode, smc);
}

// ---------------- gather-aggregate (warp/node, HFMA2 accumulation) --------
__device__ __forceinline__ void acc_row_h(__half2& a0, __half2& a1,
                                          const __half2* row, int sbits) {
    uint2 u = __ldg((const uint2*)row);
    __half2 s2 = *(__half2*)&sbits;
    a0 = __hfma2(*(__half2*)&u.x, s2, a0);
    a1 = __hfma2(*(__half2*)&u.y, s2, a1);
}

template <bool FUSE_HEAD>
__global__ void __launch_bounds__(256) k_agg(const float* __restrict__ b2,
                                             const float* __restrict__ Wl,
                                             const float* __restrict__ bl,
                                             float* __restrict__ out) {
    __shared__ float Wls[FUSE_HEAD ? NCLS * DIM : 1];
    __shared__ float bls[FUSE_HEAD ? NCLS : 1];
    const int tid  = threadIdx.x;
    const int lane = tid & 31;

    if (FUSE_HEAD) {
        for (int i4 = tid; i4 < NCLS * DIM / 4; i4 += 256)
            ((float4*)Wls)[i4] = ((const float4*)Wl)[i4];
        if (tid < NCLS) bls[tid] = bl[tid];
        __syncthreads();
    }

    const int r = (blockIdx.x * 256 + tid) >> 5;
    if (r >= NNODES) return;

    const int beg = g_off[r], end = g_off[r + 1];
    const float dr = g_dinv[r];

    __half2 a0 = __floats2half2_rn(0.f, 0.f);
    __half2 a1 = a0;
    {   // self-loop: weight dinv[r]
        __half2 h = __floats2half2_rn(dr, dr);
        acc_row_h(a0, a1, &g_hs2[(size_t)r * 64 + lane * 2], *(int*)&h);
    }

    int j = beg;
    for (; j + 8 <= end; j += 8) {
        int2 e[8];
        #pragma unroll
        for (int q = 0; q < 8; q++) e[q] = __ldg(&g_csr2[j + q]);
        #pragma unroll
        for (int q = 0; q < 8; q++)
            acc_row_h(a0, a1, &g_hs2[(size_t)e[q].x * 64 + lane * 2], e[q].y);
    }
    for (; j + 4 <= end; j += 4) {
        int2 e[4];
        #pragma unroll
        for (int q = 0; q < 4; q++) e[q] = __ldg(&g_csr2[j + q]);
        #pragma unroll
        for (int q = 0; q < 4; q++)
            acc_row_h(a0, a1, &g_hs2[(size_t)e[q].x * 64 + lane * 2], e[q].y);
    }
    for (; j < end; ++j) {
        int2 e = __ldg(&g_csr2[j]);
        acc_row_h(a0, a1, &g_hs2[(size_t)e.x * 64 + lane * 2], e.y);
    }

    if (!FUSE_HEAD) {
        uint2 o;
        *(__half2*)&o.x = a0;
        *(__half2*)&o.y = a1;
        *(uint2*)&g_ag2[(size_t)r * 64 + lane * 2] = o;   // already scaled? NO:
        // note: stored acc excludes the outer dinv[dst] factor by design —
        // gemm mode 1 applies di = g_dinv[r] exactly as before.
        return;
    }

    // ---- fused head: relu(acc*dr + b2) @ Wl^T + bl -> log_softmax ----
    float2 f0 = __half22float2(a0);
    float2 f1 = __half22float2(a1);
    float4 bv = *(const float4*)&b2[lane * 4];
    float4 v;
    v.x = fmaxf(fmaf(f0.x, dr, bv.x), 0.f);
    v.y = fmaxf(fmaf(f0.y, dr, bv.y), 0.f);
    v.z = fmaxf(fmaf(f1.x, dr, bv.z), 0.f);
    v.w = fmaxf(fmaf(f1.y, dr, bv.w), 0.f);

    float ml0 = 0.f, ml1 = -1e30f;
    #pragma unroll
    for (int c = 0; c < NCLS; c++) {
        float4 w = *(const float4*)&Wls[c * DIM + lane * 4];
        float p = v.x * w.x + v.y * w.y + v.z * w.z + v.w * w.w;
        #pragma unroll
        for (int s = 16; s > 0; s >>= 1)
            p += __shfl_xor_sync(0xffffffffu, p, s);
        p += bls[c];
        if (c < 32) { if (lane == c)      ml0 = p; }
        else        { if (lane == c - 32) ml1 = p; }
    }

    float m = fmaxf(ml0, ml1);
    #pragma unroll
    for (int s = 16; s > 0; s >>= 1)
        m = fmaxf(m, __shfl_xor_sync(0xffffffffu, m, s));
    float e = __expf(ml0 - m) + ((lane < 8) ? __expf(ml1 - m) : 0.f);
    #pragma unroll
    for (int s = 16; s > 0; s >>= 1)
        e += __shfl_xor_sync(0xffffffffu, e, s);
    float ls = __logf(e);

    out[(size_t)r * NCLS + lane] = ml0 - m - ls;
    if (lane < 8)
        out[(size_t)r * NCLS + 32 + lane] = ml1 - m - ls;
}

// ---------------- launch ---------------------------------------------------
extern "C" void kernel_launch(void* const* d_in, const int* in_sizes, int n_in,
                              void* d_out, int out_size) {
    const float* x  = (const float*)d_in[0];
    const void*  ei = d_in[1];
    const float* W1 = (const float*)d_in[2];
    const float* b1 = (const float*)d_in[3];
    const float* W2 = (const float*)d_in[4];
    const float* b2 = (const float*)d_in[5];
    const float* Wl = (const float*)d_in[6];
    const float* bl = (const float*)d_in[7];
    float* out = (float*)d_out;

    const long long E = in_sizes[1] / 2;

    cudaFuncSetAttribute(k_gemm, cudaFuncAttributeMaxDynamicSharedMemorySize,
                         GEMM_SMEM);
    cudaFuncSetAttribute(k_gemm_fill, cudaFuncAttributeMaxDynamicSharedMemorySize,
                         GEMM_SMEM);

    const int NB_E2   = (int)((E + 511) / 512);
    const int NB_GEMM = (NNODES + 63) / 64;
    const int NB_AGG  = (NNODES * 32 + 255) / 256;

    __half2* w1h; cudaGetSymbolAddress((void**)&w1h, g_w1h);
    __half2* w2h; cudaGetSymbolAddress((void**)&w2h, g_w2h);

    k_cnt<<<NB_E2, 256>>>(ei, E, W1, W2);                                   // 1
    k_scan<<<NSB, SCAN_B>>>();                                              // 2
    k_gemm_fill<<<NB_GEMM + NB_E2, 256, GEMM_SMEM>>>(x, w1h, ei, E, NB_GEMM); // 3
    k_agg<false><<<NB_AGG, 256>>>(nullptr, nullptr, nullptr, nullptr);      // 4 <- profiled
    k_gemm<<<NB_GEMM, 256, GEMM_SMEM>>>(x, w2h, b1, 1);                     // 5
    k_agg<true><<<NB_AGG, 256>>>(b2, Wl, bl, out);                          // 6
}

// round 14
// speedup vs baseline: 1.5759x; 1.5759x over previous
#include <cuda_runtime.h>
#include <cuda_fp16.h>
#include <math.h>

#define NNODES 50000
#define DIM    128
#define NCLS   40
#define EMAX   600000
#define SCAN_B 1024
#define NSB    ((NNODES + SCAN_B - 1) / SCAN_B)

// ---------------- device scratch ------------------------------------------
__device__ unsigned g_epoch = 0;
__device__ int     g_cnt[NNODES];
__device__ int     g_cur[NNODES];
__device__ int     g_off[NNODES + 1];
__device__ unsigned long long g_state[NSB];
__device__ int2    g_csr2[EMAX];                 // {src, half2(dinv[src]) bits}
__device__ float   g_dinv[NNODES];
__device__ __half2 g_w1h[DIM * DIM / 2];
__device__ __half2 g_w2h[DIM * DIM / 2];
__device__ __half2 g_hs2[NNODES * (DIM / 2)];    // RAW features h, fp16
__device__ __half2 g_ag2[NNODES * (DIM / 2)];    // aggregation (excl. dinv[dst])

__device__ __forceinline__ int detect64_block(const int* ei) {
    __shared__ int s_is64;
    if (threadIdx.x == 0) {
        int nz = 0;
        #pragma unroll
        for (int j = 0; j < 16; j++) nz += (ei[2 * j + 1] != 0);
        s_is64 = (nz == 0) ? 1 : 0;
    }
    __syncthreads();
    return s_is64;
}

// ---------------- cnt (+ W->fp16, + epoch bump) ---------------------------
__global__ void k_cnt(const void* ei, long long E,
                      const float* __restrict__ W1, const float* __restrict__ W2) {
    const int is64 = detect64_block((const int*)ei);
    int gid = blockIdx.x * 256 + threadIdx.x;
    if (gid == 0) atomicAdd(&g_epoch, 1u);
    if (gid < DIM * DIM / 2) {
        float2 a = *(const float2*)&W1[2 * gid];
        float2 b = *(const float2*)&W2[2 * gid];
        g_w1h[gid] = __floats2half2_rn(a.x, a.y);
        g_w2h[gid] = __floats2half2_rn(b.x, b.y);
    }
    long long base = (long long)gid * 2;
    if (base >= E) return;
    int d0, d1; bool two = (base + 1 < E);
    if (is64) {
        const long long* pd = (const long long*)ei + E;
        if (two) { longlong2 v = *(const longlong2*)&pd[base]; d0 = (int)v.x; d1 = (int)v.y; }
        else d0 = (int)pd[base];
    } else {
        const int* pd = (const int*)ei + (size_t)E;
        if (two) { int2 v = *(const int2*)&pd[base]; d0 = v.x; d1 = v.y; }
        else d0 = pd[base];
    }
    atomicAdd(&g_cnt[d0], 1);
    if (two) atomicAdd(&g_cnt[d1], 1);
}

// ------- one-pass epoch-tagged lookback scan (+dinv, +cursors, cnt reset) --
__global__ void __launch_bounds__(SCAN_B) k_scan() {
    __shared__ int wsum[32];
    __shared__ int s_run;
    const int tid = threadIdx.x, lane = tid & 31, wid = tid >> 5;
    const int bid = blockIdx.x;
    const int i = bid * SCAN_B + tid;

    const unsigned e = g_epoch;
    const unsigned long long flagP = (unsigned long long)(2u * e + 1u) << 32;
    const unsigned long long flagF = (unsigned long long)(2u * e + 2u) << 32;

    int v = (i < NNODES) ? g_cnt[i] : 0;
    if (i < NNODES) {
        g_dinv[i] = rsqrtf((float)(v + 1));
        g_cnt[i] = 0;
    }

    int incl = v;
    #pragma unroll
    for (int s = 1; s < 32; s <<= 1) {
        int t = __shfl_up_sync(0xffffffffu, incl, s);
        if (lane >= s) incl += t;
    }
    if (lane == 31) wsum[wid] = incl;
    __syncthreads();
    if (wid == 0) {
        int w = wsum[lane];
        int wi = w;
        #pragma unroll
        for (int s = 1; s < 32; s <<= 1) {
            int t = __shfl_up_sync(0xffffffffu, wi, s);
            if (lane >= s) wi += t;
        }
        wsum[lane] = wi - w;
    }
    __syncthreads();
    int excl = incl - v + wsum[wid];

    if (tid == SCAN_B - 1) {
        int total = excl + v;
        long long run = 0;
        if (bid == 0) {
            atomicExch(&g_state[0], flagF | (unsigned)total);
        } else {
            atomicExch(&g_state[bid], flagP | (unsigned)total);
            int p = bid - 1;
            while (true) {
                unsigned long long st = atomicAdd(&g_state[p], 0ULL);
                unsigned long long f = st & 0xFFFFFFFF00000000ULL;
                if (f == flagF) { run += (int)(unsigned)st; break; }
                if (f == flagP) { run += (int)(unsigned)st; --p; continue; }
                __nanosleep(20);
            }
            atomicExch(&g_state[bid], flagF | (unsigned)(run + total));
        }
        s_run = (int)run;
        if (bid == NSB - 1) g_off[NNODES] = (int)run + total;
    }
    __syncthreads();
    if (i < NNODES) {
        int o = excl + s_run;
        g_off[i] = o;
        g_cur[i] = o;
    }
}

// ---------------- fill body ------------------------------------------------
__device__ __forceinline__ void fill_body(int bx, const void* ei, long long E,
                                          int is64) {
    long long base = ((long long)bx * 256 + threadIdx.x) * 2;
    if (base >= E) return;
    int s0, s1, d0, d1; bool two = (base + 1 < E);
    if (is64) {
        const long long* ps = (const long long*)ei;
        const long long* pd = ps + E;
        if (two) {
            longlong2 vs = *(const longlong2*)&ps[base];
            longlong2 vd = *(const longlong2*)&pd[base];
            s0 = (int)vs.x; s1 = (int)vs.y; d0 = (int)vd.x; d1 = (int)vd.y;
        } else { s0 = (int)ps[base]; d0 = (int)pd[base]; }
    } else {
        const int* ps = (const int*)ei;
        const int* pd = ps + (size_t)E;
        if (two) {
            int2 vs = *(const int2*)&ps[base];
            int2 vd = *(const int2*)&pd[base];
            s0 = vs.x; s1 = vs.y; d0 = vd.x; d1 = vd.y;
        } else { s0 = ps[base]; d0 = pd[base]; }
    }
    float f0 = __ldg(&g_dinv[s0]);
    float f1 = two ? __ldg(&g_dinv[s1]) : 0.f;
    __half2 h0 = __floats2half2_rn(f0, f0);
    __half2 h1 = __floats2half2_rn(f1, f1);
    int p0 = atomicAdd(&g_cur[d0], 1);
    int p1 = two ? atomicAdd(&g_cur[d1], 1) : 0;
    g_csr2[p0] = make_int2(s0, *(int*)&h0);
    if (two) g_csr2[p1] = make_int2(s1, *(int*)&h1);
}

// ---------------- tensor-core GEMM body (swizzled, 64-row tile) -----------
#define A_BYTES (64 * 256)
#define GEMM_SMEM (A_BYTES + 128 * 256)

__device__ __forceinline__ unsigned sw_off(int r, int chunk) {
    return (unsigned)(r * 256 + ((chunk ^ (r & 7)) << 4));
}

__device__ void gemm_body(int bx, const float* __restrict__ x,
                          const __half2* __restrict__ Wh,
                          const float* __restrict__ bias,
                          int mode, char* smc) {
    char* Asb = smc;
    char* Wsb = smc + A_BYTES;
    const int tid = threadIdx.x;
    const int r0  = bx * 64;

    #pragma unroll
    for (int j = 0; j < 8; j++) {
        int chunk = tid + j * 256;
        int c  = chunk >> 4;
        int k8 = chunk & 15;
        uint4 u = *(const uint4*)((const char*)Wh + (size_t)chunk * 16);
        *(uint4*)(Wsb + sw_off(c, k8)) = u;
    }
    #pragma unroll
    for (int j = 0; j < 8; j++) {
        int flat = (tid + j * 256) * 4;
        int rl = flat >> 7, k = flat & 127;
        int r = r0 + rl;
        float4 v = make_float4(0.f, 0.f, 0.f, 0.f);
        if (r < NNODES) {
            if (mode == 0) {
                v = *(const float4*)&x[(size_t)r * DIM + k];
            } else {
                uint2 u = *(const uint2*)&g_ag2[(size_t)r * 64 + (k >> 1)];
                float2 a0 = __half22float2(*(const __half2*)&u.x);
                float2 a1 = __half22float2(*(const __half2*)&u.y);
                float4 b = *(const float4*)&bias[k];
                float di = g_dinv[r];
                v.x = fmaxf(fmaf(a0.x, di, b.x), 0.f);
                v.y = fmaxf(fmaf(a0.y, di, b.y), 0.f);
                v.z = fmaxf(fmaf(a1.x, di, b.z), 0.f);
                v.w = fmaxf(fmaf(a1.y, di, b.w), 0.f);
            }
        }
        uint2 u;
        *(__half2*)&u.x = __floats2half2_rn(v.x, v.y);
        *(__half2*)&u.y = __floats2half2_rn(v.z, v.w);
        *(uint2*)(Asb + sw_off(rl, k >> 3) + ((k & 7) << 1)) = u;
    }
    __syncthreads();

    const int warp = tid >> 5, lane = tid & 31;
    const int m0 = (warp >> 1) * 16;
    const int n0 = (warp & 1) * 64;
    const int gid = lane >> 2, tig = lane & 3;

    float acc[8][4];
    #pragma unroll
    for (int t = 0; t < 8; t++)
        #pragma unroll
        for (int q = 0; q < 4; q++) acc[t][q] = 0.f;

    unsigned aSm = (unsigned)__cvta_generic_to_shared(Asb);
    unsigned wSm = (unsigned)__cvta_generic_to_shared(Wsb);
    const int aRow = m0 + (lane & 15);
    const int aChA = (lane & 16) ? 1 : 0;
    const int bRow = ((lane & 16) ? 8 : 0) + (lane & 7);
    const int bChA = (lane & 8) ? 1 : 0;

    #pragma unroll
    for (int ks = 0; ks < 8; ks++) {
        unsigned a0, a1, a2, a3;
        unsigned aAddr = aSm + sw_off(aRow, 2 * ks + aChA);
        asm volatile("ldmatrix.sync.aligned.m8n8.x4.shared.b16 {%0,%1,%2,%3},[%4];"
                     : "=r"(a0), "=r"(a1), "=r"(a2), "=r"(a3) : "r"(aAddr));
        #pragma unroll
        for (int tp = 0; tp < 4; tp++) {
            unsigned b0, b1, b2, b3;
            unsigned bAddr = wSm + sw_off(n0 + 16 * tp + bRow, 2 * ks + bChA);
            asm volatile("ldmatrix.sync.aligned.m8n8.x4.shared.b16 {%0,%1,%2,%3},[%4];"
                         : "=r"(b0), "=r"(b1), "=r"(b2), "=r"(b3) : "r"(bAddr));
            asm volatile("mma.sync.aligned.m16n8k16.row.col.f32.f16.f16.f32 "
                         "{%0,%1,%2,%3},{%4,%5,%6,%7},{%8,%9},{%0,%1,%2,%3};"
                         : "+f"(acc[2 * tp][0]), "+f"(acc[2 * tp][1]),
                           "+f"(acc[2 * tp][2]), "+f"(acc[2 * tp][3])
                         : "r"(a0), "r"(a1), "r"(a2), "r"(a3), "r"(b0), "r"(b1));
            asm volatile("mma.sync.aligned.m16n8k16.row.col.f32.f16.f16.f32 "
                         "{%0,%1,%2,%3},{%4,%5,%6,%7},{%8,%9},{%0,%1,%2,%3};"
                         : "+f"(acc[2 * tp + 1][0]), "+f"(acc[2 * tp + 1][1]),
                           "+f"(acc[2 * tp + 1][2]), "+f"(acc[2 * tp + 1][3])
                         : "r"(a0), "r"(a1), "r"(a2), "r"(a3), "r"(b2), "r"(b3));
        }
    }

    const int r1 = r0 + m0 + gid;
    const int r2 = r1 + 8;
    #pragma unroll
    for (int t = 0; t < 8; t++) {
        int ci = (n0 >> 1) + 4 * t + tig;
        if (r1 < NNODES)
            g_hs2[(size_t)r1 * 64 + ci] = __floats2half2_rn(acc[t][0], acc[t][1]);
        if (r2 < NNODES)
            g_hs2[(size_t)r2 * 64 + ci] = __floats2half2_rn(acc[t][2], acc[t][3]);
    }
}

__global__ void __launch_bounds__(256, 4) k_gemm_fill(const float* __restrict__ x,
                                                      const __half2* __restrict__ Wh,
                                                      const void* ei, long long E,
                                                      int nGemm) {
    extern __shared__ char smc[];
    if (blockIdx.x < nGemm) {
        gemm_body(blockIdx.x, x, Wh, nullptr, 0, smc);
    } else {
        const int is64 = detect64_block((const int*)ei);
        fill_body(blockIdx.x - nGemm, ei, E, is64);
    }
}

__global__ void __launch_bounds__(256, 4) k_gemm(const float* __restrict__ x,
                                                 const __half2* __restrict__ Wh,
                                                 const float* __restrict__ bias,
                                                 int mode) {
    extern __shared__ char smc[];
    gemm_body(blockIdx.x, x, Wh, bias, mode, smc);
}

// ---------------- gather-aggregate (warp/node, HFMA2, no head) ------------
__device__ __forceinline__ void acc_row_h(__half2& a0, __half2& a1,
                                          const __half2* row, int sbits) {
    uint2 u = __ldg((const uint2*)row);
    __half2 s2 = *(__half2*)&sbits;
    a0 = __hfma2(*(__half2*)&u.x, s2, a0);
    a1 = __hfma2(*(__half2*)&u.y, s2, a1);
}

__global__ void __launch_bounds__(256) k_agg() {
    const int tid  = threadIdx.x;
    const int lane = tid & 31;
    const int r = (blockIdx.x * 256 + tid) >> 5;
    if (r >= NNODES) return;

    const int beg = g_off[r], end = g_off[r + 1];
    const float dr = g_dinv[r];

    __half2 a0 = __floats2half2_rn(0.f, 0.f);
    __half2 a1 = a0;
    {   // self-loop
        __half2 h = __floats2half2_rn(dr, dr);
        acc_row_h(a0, a1, &g_hs2[(size_t)r * 64 + lane * 2], *(int*)&h);
    }

    int j = beg;
    for (; j + 8 <= end; j += 8) {
        int2 e[8];
        #pragma unroll
        for (int q = 0; q < 8; q++) e[q] = __ldg(&g_csr2[j + q]);
        #pragma unroll
        for (int q = 0; q < 8; q++)
            acc_row_h(a0, a1, &g_hs2[(size_t)e[q].x * 64 + lane * 2], e[q].y);
    }
    for (; j + 4 <= end; j += 4) {
        int2 e[4];
        #pragma unroll
        for (int q = 0; q < 4; q++) e[q] = __ldg(&g_csr2[j + q]);
        #pragma unroll
        for (int q = 0; q < 4; q++)
            acc_row_h(a0, a1, &g_hs2[(size_t)e[q].x * 64 + lane * 2], e[q].y);
    }
    for (; j < end; ++j) {
        int2 e = __ldg(&g_csr2[j]);
        acc_row_h(a0, a1, &g_hs2[(size_t)e.x * 64 + lane * 2], e.y);
    }

    uint2 o;
    *(__half2*)&o.x = a0;
    *(__half2*)&o.y = a1;
    *(uint2*)&g_ag2[(size_t)r * 64 + lane * 2] = o;
}

// ---------------- head: relu(ag2*dr+b2) @ Wl^T + bl -> log_softmax --------
// 128-row tiles, 8 warps (warp = 16 rows x 64 cols). Wl padded 40->64 rows.
#define HEAD_A_BYTES (128 * 256)
#define HEAD_SMEM (HEAD_A_BYTES + 64 * 256)

__global__ void __launch_bounds__(256, 4) k_head(const float* __restrict__ b2,
                                                 const float* __restrict__ Wl,
                                                 const float* __restrict__ bl,
                                                 float* __restrict__ out) {
    extern __shared__ char smc[];
    char* Asb = smc;
    char* Wsb = smc + HEAD_A_BYTES;
    const int tid = threadIdx.x;
    const int r0  = blockIdx.x * 128;

    // zero pad rows 40..63 of W tile (24 rows x 16 chunks = 384 uint4)
    for (int idx = tid; idx < 384; idx += 256) {
        int c = 40 + (idx >> 4), k8 = idx & 15;
        *(uint4*)(Wsb + sw_off(c, k8)) = make_uint4(0, 0, 0, 0);
    }
    // stage Wl rows 0..39 (40*128 floats = 1280 float4)
    for (int idx = tid; idx < 1280; idx += 256) {
        int flat = idx * 4;
        int c = flat >> 7, k = flat & 127;
        float4 w = *(const float4*)&Wl[c * 128 + k];
        uint2 u;
        *(__half2*)&u.x = __floats2half2_rn(w.x, w.y);
        *(__half2*)&u.y = __floats2half2_rn(w.z, w.w);
        *(uint2*)(Wsb + sw_off(c, k >> 3) + ((k & 7) << 1)) = u;
    }
    // stage A = relu(ag2*dr + b2), 128 rows
    #pragma unroll
    for (int j = 0; j < 16; j++) {
        int flat = (tid + j * 256) * 4;
        int rl = flat >> 7, k = flat & 127;
        int r = r0 + rl;
        float4 v = make_float4(0.f, 0.f, 0.f, 0.f);
        if (r < NNODES) {
            uint2 u = *(const uint2*)&g_ag2[(size_t)r * 64 + (k >> 1)];
            float2 a0 = __half22float2(*(const __half2*)&u.x);
            float2 a1 = __half22float2(*(const __half2*)&u.y);
            float4 b = *(const float4*)&b2[k];
            float di = g_dinv[r];
            v.x = fmaxf(fmaf(a0.x, di, b.x), 0.f);
            v.y = fmaxf(fmaf(a0.y, di, b.y), 0.f);
            v.z = fmaxf(fmaf(a1.x, di, b.z), 0.f);
            v.w = fmaxf(fmaf(a1.y, di, b.w), 0.f);
        }
        uint2 u;
        *(__half2*)&u.x = __floats2half2_rn(v.x, v.y);
        *(__half2*)&u.y = __floats2half2_rn(v.z, v.w);
        *(uint2*)(Asb + sw_off(rl, k >> 3) + ((k & 7) << 1)) = u;
    }
    __syncthreads();

    const int warp = tid >> 5, lane = tid & 31;
    const int m0 = warp * 16;           // 8 warps x 16 rows = 128 rows
    const int gid = lane >> 2, tig = lane & 3;

    float acc[8][4];
    #pragma unroll
    for (int t = 0; t < 8; t++)
        #pragma unroll
        for (int q = 0; q < 4; q++) acc[t][q] = 0.f;

    unsigned aSm = (unsigned)__cvta_generic_to_shared(Asb);
    unsigned wSm = (unsigned)__cvta_generic_to_shared(Wsb);
    const int aRow = m0 + (lane & 15);
    const int aChA = (lane & 16) ? 1 : 0;
    const int bRow = ((lane & 16) ? 8 : 0) + (lane & 7);
    const int bChA = (lane & 8) ? 1 : 0;

    #pragma unroll
    for (int ks = 0; ks < 8; ks++) {
        unsigned a0, a1, a2, a3;
        unsigned aAddr = aSm + sw_off(aRow, 2 * ks + aChA);
        asm volatile("ldmatrix.sync.aligned.m8n8.x4.shared.b16 {%0,%1,%2,%3},[%4];"
                     : "=r"(a0), "=r"(a1), "=r"(a2), "=r"(a3) : "r"(aAddr));
        #pragma unroll
        for (int tp = 0; tp < 4; tp++) {
            unsigned b0, b1, b2, b3;
            unsigned bAddr = wSm + sw_off(16 * tp + bRow, 2 * ks + bChA);
            asm volatile("ldmatrix.sync.aligned.m8n8.x4.shared.b16 {%0,%1,%2,%3},[%4];"
                         : "=r"(b0), "=r"(b1), "=r"(b2), "=r"(b3) : "r"(bAddr));
            asm volatile("mma.sync.aligned.m16n8k16.row.col.f32.f16.f16.f32 "
                         "{%0,%1,%2,%3},{%4,%5,%6,%7},{%8,%9},{%0,%1,%2,%3};"
                         : "+f"(acc[2 * tp][0]), "+f"(acc[2 * tp][1]),
                           "+f"(acc[2 * tp][2]), "+f"(acc[2 * tp][3])
                         : "r"(a0), "r"(a1), "r"(a2), "r"(a3), "r"(b0), "r"(b1));
            asm volatile("mma.sync.aligned.m16n8k16.row.col.f32.f16.f16.f32 "
                         "{%0,%1,%2,%3},{%4,%5,%6,%7},{%8,%9},{%0,%1,%2,%3};"
                         : "+f"(acc[2 * tp + 1][0]), "+f"(acc[2 * tp + 1][1]),
                           "+f"(acc[2 * tp + 1][2]), "+f"(acc[2 * tp + 1][3])
                         : "r"(a0), "r"(a1), "r"(a2), "r"(a3), "r"(b2), "r"(b3));
        }
    }

    // epilogue: lane holds row r1 cols {8t+2tig, +1} (t<5 valid: cols 0..39),
    // row r2 same in acc[t][2..3]. Reduce max/sum across the 4-lane group.
    const int r1 = r0 + m0 + gid;
    const int r2 = r1 + 8;

    float lg1[5][2], lg2[5][2];
    float m1 = -1e30f, m2 = -1e30f;
    #pragma unroll
    for (int t = 0; t < 5; t++) {
        int c = 8 * t + 2 * tig;
        float bl0 = __ldg(&bl[c]);
        float bl1 = __ldg(&bl[c + 1]);
        lg1[t][0] = acc[t][0] + bl0; lg1[t][1] = acc[t][1] + bl1;
        lg2[t][0] = acc[t][2] + bl0; lg2[t][1] = acc[t][3] + bl1;
        m1 = fmaxf(m1, fmaxf(lg1[t][0], lg1[t][1]));
        m2 = fmaxf(m2, fmaxf(lg2[t][0], lg2[t][1]));
    }
    #pragma unroll
    for (int s = 1; s <= 2; s <<= 1) {
        m1 = fmaxf(m1, __shfl_xor_sync(0xffffffffu, m1, s));
        m2 = fmaxf(m2, __shfl_xor_sync(0xffffffffu, m2, s));
    }
    float e1 = 0.f, e2 = 0.f;
    #pragma unroll
    for (int t = 0; t < 5; t++) {
        e1 += __expf(lg1[t][0] - m1) + __expf(lg1[t][1] - m1);
        e2 += __expf(lg2[t][0] - m2) + __expf(lg2[t][1] - m2);
    }
    #pragma unroll
    for (int s = 1; s <= 2; s <<= 1) {
        e1 += __shfl_xor_sync(0xffffffffu, e1, s);
        e2 += __shfl_xor_sync(0xffffffffu, e2, s);
    }
    float ls1 = m1 + __logf(e1);
    float ls2 = m2 + __logf(e2);

    #pragma unroll
    for (int t = 0; t < 5; t++) {
        int c = 8 * t + 2 * tig;
        if (r1 < NNODES) {
            float2 o = make_float2(lg1[t][0] - ls1, lg1[t][1] - ls1);
            *(float2*)&out[(size_t)r1 * NCLS + c] = o;
        }
        if (r2 < NNODES) {
            float2 o = make_float2(lg2[t][0] - ls2, lg2[t][1] - ls2);
            *(float2*)&out[(size_t)r2 * NCLS + c] = o;
        }
    }
}

// ---------------- launch ---------------------------------------------------
extern "C" void kernel_launch(void* const* d_in, const int* in_sizes, int n_in,
                              void* d_out, int out_size) {
    const float* x  = (const float*)d_in[0];
    const void*  ei = d_in[1];
    const float* W1 = (const float*)d_in[2];
    const float* b1 = (const float*)d_in[3];
    const float* W2 = (const float*)d_in[4];
    const float* b2 = (const float*)d_in[5];
    const float* Wl = (const float*)d_in[6];
    const float* bl = (const float*)d_in[7];
    float* out = (float*)d_out;

    const long long E = in_sizes[1] / 2;

    cudaFuncSetAttribute(k_gemm, cudaFuncAttributeMaxDynamicSharedMemorySize,
                         GEMM_SMEM);
    cudaFuncSetAttribute(k_gemm_fill, cudaFuncAttributeMaxDynamicSharedMemorySize,
                         GEMM_SMEM);
    cudaFuncSetAttribute(k_head, cudaFuncAttributeMaxDynamicSharedMemorySize,
                         HEAD_SMEM);

    const int NB_E2   = (int)((E + 511) / 512);
    const int NB_GEMM = (NNODES + 63) / 64;
    const int NB_AGG  = (NNODES * 32 + 255) / 256;
    const int NB_HEAD = (NNODES + 127) / 128;

    __half2* w1h; cudaGetSymbolAddress((void**)&w1h, g_w1h);
    __half2* w2h; cudaGetSymbolAddress((void**)&w2h, g_w2h);

    k_cnt<<<NB_E2, 256>>>(ei, E, W1, W2);                                     // 1
    k_scan<<<NSB, SCAN_B>>>();                                                // 2
    k_gemm_fill<<<NB_GEMM + NB_E2, 256, GEMM_SMEM>>>(x, w1h, ei, E, NB_GEMM); // 3
    k_agg<<<NB_AGG, 256>>>();                                                 // 4
    k_gemm<<<NB_GEMM, 256, GEMM_SMEM>>>(x, w2h, b1, 1);                       // 5
    k_agg<<<NB_AGG, 256>>>();                                                 // 6
    k_head<<<NB_HEAD, 256, HEAD_SMEM>>>(b2, Wl, bl, out);                     // 7
}

// round 15
// speedup vs baseline: 1.6410x; 1.0414x over previous
#include <cuda_runtime.h>
#include <cuda_fp16.h>
#include <math.h>

#define NNODES 50000
#define DIM    128
#define NCLS   40
#define EMAX   600000
#define SCAN_B 1024
#define NSB    ((NNODES + SCAN_B - 1) / SCAN_B)

// ---------------- device scratch ------------------------------------------
__device__ unsigned g_epoch = 0;
__device__ int     g_cnt[NNODES];
__device__ int     g_cur[NNODES];
__device__ int     g_off[NNODES + 1];
__device__ unsigned long long g_state[NSB];
__device__ int2    g_csr2[EMAX];                 // {src, half2(dinv[src]) bits}
__device__ float   g_dinv[NNODES];
__device__ __half2 g_w2h[DIM * DIM / 2];
__device__ __half2 g_hs2[NNODES * (DIM / 2)];    // RAW features h, fp16
__device__ __half2 g_ag2[NNODES * (DIM / 2)];    // aggregation (excl. dinv[dst])

__device__ __forceinline__ int detect64_block(const int* ei) {
    __shared__ int s_is64;
    if (threadIdx.x == 0) {
        int nz = 0;
        #pragma unroll
        for (int j = 0; j < 16; j++) nz += (ei[2 * j + 1] != 0);
        s_is64 = (nz == 0) ? 1 : 0;
    }
    __syncthreads();
    return s_is64;
}

// ---------------- swizzle --------------------------------------------------
__device__ __forceinline__ unsigned sw_off(int r, int chunk) {
    return (unsigned)(r * 256 + ((chunk ^ (r & 7)) << 4));
}

// ---------------- tensor-core GEMM body (swizzled, 64-row tile) -----------
#define A_BYTES (64 * 256)
#define GEMM_SMEM (A_BYTES + 128 * 256)

__device__ void gemm_body(int bx, const float* __restrict__ x,
                          const __half2* __restrict__ Wh,
                          const float* __restrict__ Wf,
                          const float* __restrict__ bias,
                          int mode, char* smc) {
    char* Asb = smc;
    char* Wsb = smc + A_BYTES;
    const int tid = threadIdx.x;
    const int r0  = bx * 64;

    if (Wf) {
        // stage W from fp32 with conversion (gemm1 path, avoids race on g_w1h)
        #pragma unroll
        for (int j = 0; j < 16; j++) {
            int flat = (tid + j * 256) * 4;
            int c = flat >> 7, k = flat & 127;
            float4 w = *(const float4*)&Wf[c * 128 + k];
            uint2 u;
            *(__half2*)&u.x = __floats2half2_rn(w.x, w.y);
            *(__half2*)&u.y = __floats2half2_rn(w.z, w.w);
            *(uint2*)(Wsb + sw_off(c, k >> 3) + ((k & 7) << 1)) = u;
        }
    } else {
        // stage prestaged fp16 W: 2048 16B chunks
        #pragma unroll
        for (int j = 0; j < 8; j++) {
            int chunk = tid + j * 256;
            int c  = chunk >> 4;
            int k8 = chunk & 15;
            uint4 u = *(const uint4*)((const char*)Wh + (size_t)chunk * 16);
            *(uint4*)(Wsb + sw_off(c, k8)) = u;
        }
    }
    #pragma unroll
    for (int j = 0; j < 8; j++) {
        int flat = (tid + j * 256) * 4;
        int rl = flat >> 7, k = flat & 127;
        int r = r0 + rl;
        float4 v = make_float4(0.f, 0.f, 0.f, 0.f);
        if (r < NNODES) {
            if (mode == 0) {
                v = *(const float4*)&x[(size_t)r * DIM + k];
            } else {
                uint2 u = *(const uint2*)&g_ag2[(size_t)r * 64 + (k >> 1)];
                float2 a0 = __half22float2(*(const __half2*)&u.x);
                float2 a1 = __half22float2(*(const __half2*)&u.y);
                float4 b = *(const float4*)&bias[k];
                float di = g_dinv[r];
                v.x = fmaxf(fmaf(a0.x, di, b.x), 0.f);
                v.y = fmaxf(fmaf(a0.y, di, b.y), 0.f);
                v.z = fmaxf(fmaf(a1.x, di, b.z), 0.f);
                v.w = fmaxf(fmaf(a1.y, di, b.w), 0.f);
            }
        }
        uint2 u;
        *(__half2*)&u.x = __floats2half2_rn(v.x, v.y);
        *(__half2*)&u.y = __floats2half2_rn(v.z, v.w);
        *(uint2*)(Asb + sw_off(rl, k >> 3) + ((k & 7) << 1)) = u;
    }
    __syncthreads();

    const int warp = tid >> 5, lane = tid & 31;
    const int m0 = (warp >> 1) * 16;
    const int n0 = (warp & 1) * 64;
    const int gid = lane >> 2, tig = lane & 3;

    float acc[8][4];
    #pragma unroll
    for (int t = 0; t < 8; t++)
        #pragma unroll
        for (int q = 0; q < 4; q++) acc[t][q] = 0.f;

    unsigned aSm = (unsigned)__cvta_generic_to_shared(Asb);
    unsigned wSm = (unsigned)__cvta_generic_to_shared(Wsb);
    const int aRow = m0 + (lane & 15);
    const int aChA = (lane & 16) ? 1 : 0;
    const int bRow = ((lane & 16) ? 8 : 0) + (lane & 7);
    const int bChA = (lane & 8) ? 1 : 0;

    #pragma unroll
    for (int ks = 0; ks < 8; ks++) {
        unsigned a0, a1, a2, a3;
        unsigned aAddr = aSm + sw_off(aRow, 2 * ks + aChA);
        asm volatile("ldmatrix.sync.aligned.m8n8.x4.shared.b16 {%0,%1,%2,%3},[%4];"
                     : "=r"(a0), "=r"(a1), "=r"(a2), "=r"(a3) : "r"(aAddr));
        #pragma unroll
        for (int tp = 0; tp < 4; tp++) {
            unsigned b0, b1, b2, b3;
            unsigned bAddr = wSm + sw_off(n0 + 16 * tp + bRow, 2 * ks + bChA);
            asm volatile("ldmatrix.sync.aligned.m8n8.x4.shared.b16 {%0,%1,%2,%3},[%4];"
                         : "=r"(b0), "=r"(b1), "=r"(b2), "=r"(b3) : "r"(bAddr));
            asm volatile("mma.sync.aligned.m16n8k16.row.col.f32.f16.f16.f32 "
                         "{%0,%1,%2,%3},{%4,%5,%6,%7},{%8,%9},{%0,%1,%2,%3};"
                         : "+f"(acc[2 * tp][0]), "+f"(acc[2 * tp][1]),
                           "+f"(acc[2 * tp][2]), "+f"(acc[2 * tp][3])
                         : "r"(a0), "r"(a1), "r"(a2), "r"(a3), "r"(b0), "r"(b1));
            asm volatile("mma.sync.aligned.m16n8k16.row.col.f32.f16.f16.f32 "
                         "{%0,%1,%2,%3},{%4,%5,%6,%7},{%8,%9},{%0,%1,%2,%3};"
                         : "+f"(acc[2 * tp + 1][0]), "+f"(acc[2 * tp + 1][1]),
                           "+f"(acc[2 * tp + 1][2]), "+f"(acc[2 * tp + 1][3])
                         : "r"(a0), "r"(a1), "r"(a2), "r"(a3), "r"(b2), "r"(b3));
        }
    }

    const int r1 = r0 + m0 + gid;
    const int r2 = r1 + 8;
    #pragma unroll
    for (int t = 0; t < 8; t++) {
        int ci = (n0 >> 1) + 4 * t + tig;
        if (r1 < NNODES)
            g_hs2[(size_t)r1 * 64 + ci] = __floats2half2_rn(acc[t][0], acc[t][1]);
        if (r2 < NNODES)
            g_hs2[(size_t)r2 * 64 + ci] = __floats2half2_rn(acc[t][2], acc[t][3]);
    }
}

// ---------------- cnt body (+ W2->fp16, + epoch bump) ---------------------
__device__ __forceinline__ void cnt_body(int bx, const void* ei, long long E,
                                         const float* __restrict__ W2, int is64) {
    int gid = bx * 256 + threadIdx.x;
    if (gid == 0) atomicAdd(&g_epoch, 1u);
    if (gid < DIM * DIM / 2) {
        float2 b = *(const float2*)&W2[2 * gid];
        g_w2h[gid] = __floats2half2_rn(b.x, b.y);
    }
    long long base = (long long)gid * 2;
    if (base >= E) return;
    int d0, d1; bool two = (base + 1 < E);
    if (is64) {
        const long long* pd = (const long long*)ei + E;
        if (two) { longlong2 v = *(const longlong2*)&pd[base]; d0 = (int)v.x; d1 = (int)v.y; }
        else d0 = (int)pd[base];
    } else {
        const int* pd = (const int*)ei + (size_t)E;
        if (two) { int2 v = *(const int2*)&pd[base]; d0 = v.x; d1 = v.y; }
        else d0 = pd[base];
    }
    atomicAdd(&g_cnt[d0], 1);
    if (two) atomicAdd(&g_cnt[d1], 1);
}

// fused: first nGemm blocks run gemm1 (W from fp32), rest run degree count
__global__ void __launch_bounds__(256, 4) k_cnt_gemm(const float* __restrict__ x,
                                                     const float* __restrict__ W1,
                                                     const float* __restrict__ W2,
                                                     const void* ei, long long E,
                                                     int nGemm) {
    extern __shared__ char smc[];
    if (blockIdx.x < nGemm) {
        gemm_body(blockIdx.x, x, nullptr, W1, nullptr, 0, smc);
    } else {
        const int is64 = detect64_block((const int*)ei);
        cnt_body(blockIdx.x - nGemm, ei, E, W2, is64);
    }
}

// ------- one-pass epoch-tagged lookback scan (+dinv, +cursors, cnt reset) --
__global__ void __launch_bounds__(SCAN_B) k_scan() {
    __shared__ int wsum[32];
    __shared__ int s_run;
    const int tid = threadIdx.x, lane = tid & 31, wid = tid >> 5;
    const int bid = blockIdx.x;
    const int i = bid * SCAN_B + tid;

    const unsigned e = g_epoch;
    const unsigned long long flagP = (unsigned long long)(2u * e + 1u) << 32;
    const unsigned long long flagF = (unsigned long long)(2u * e + 2u) << 32;

    int v = (i < NNODES) ? g_cnt[i] : 0;
    if (i < NNODES) {
        g_dinv[i] = rsqrtf((float)(v + 1));
        g_cnt[i] = 0;
    }

    int incl = v;
    #pragma unroll
    for (int s = 1; s < 32; s <<= 1) {
        int t = __shfl_up_sync(0xffffffffu, incl, s);
        if (lane >= s) incl += t;
    }
    if (lane == 31) wsum[wid] = incl;
    __syncthreads();
    if (wid == 0) {
        int w = wsum[lane];
        int wi = w;
        #pragma unroll
        for (int s = 1; s < 32; s <<= 1) {
            int t = __shfl_up_sync(0xffffffffu, wi, s);
            if (lane >= s) wi += t;
        }
        wsum[lane] = wi - w;
    }
    __syncthreads();
    int excl = incl - v + wsum[wid];

    if (tid == SCAN_B - 1) {
        int total = excl + v;
        long long run = 0;
        if (bid == 0) {
            atomicExch(&g_state[0], flagF | (unsigned)total);
        } else {
            atomicExch(&g_state[bid], flagP | (unsigned)total);
            int p = bid - 1;
            while (true) {
                unsigned long long st = atomicAdd(&g_state[p], 0ULL);
                unsigned long long f = st & 0xFFFFFFFF00000000ULL;
                if (f == flagF) { run += (int)(unsigned)st; break; }
                if (f == flagP) { run += (int)(unsigned)st; --p; continue; }
                __nanosleep(20);
            }
            atomicExch(&g_state[bid], flagF | (unsigned)(run + total));
        }
        s_run = (int)run;
        if (bid == NSB - 1) g_off[NNODES] = (int)run + total;
    }
    __syncthreads();
    if (i < NNODES) {
        int o = excl + s_run;
        g_off[i] = o;
        g_cur[i] = o;
    }
}

// ---------------- CSR fill --------------------------------------------------
__global__ void k_fill(const void* ei, long long E) {
    const int is64 = detect64_block((const int*)ei);
    long long base = ((long long)blockIdx.x * 256 + threadIdx.x) * 2;
    if (base >= E) return;
    int s0, s1, d0, d1; bool two = (base + 1 < E);
    if (is64) {
        const long long* ps = (const long long*)ei;
        const long long* pd = ps + E;
        if (two) {
            longlong2 vs = *(const longlong2*)&ps[base];
            longlong2 vd = *(const longlong2*)&pd[base];
            s0 = (int)vs.x; s1 = (int)vs.y; d0 = (int)vd.x; d1 = (int)vd.y;
        } else { s0 = (int)ps[base]; d0 = (int)pd[base]; }
    } else {
        const int* ps = (const int*)ei;
        const int* pd = ps + (size_t)E;
        if (two) {
            int2 vs = *(const int2*)&ps[base];
            int2 vd = *(const int2*)&pd[base];
            s0 = vs.x; s1 = vs.y; d0 = vd.x; d1 = vd.y;
        } else { s0 = ps[base]; d0 = pd[base]; }
    }
    float f0 = __ldg(&g_dinv[s0]);
    float f1 = two ? __ldg(&g_dinv[s1]) : 0.f;
    __half2 h0 = __floats2half2_rn(f0, f0);
    __half2 h1 = __floats2half2_rn(f1, f1);
    int p0 = atomicAdd(&g_cur[d0], 1);
    int p1 = two ? atomicAdd(&g_cur[d1], 1) : 0;
    g_csr2[p0] = make_int2(s0, *(int*)&h0);
    if (two) g_csr2[p1] = make_int2(s1, *(int*)&h1);
}

__global__ void __launch_bounds__(256, 4) k_gemm(const float* __restrict__ x,
                                                 const __half2* __restrict__ Wh,
                                                 const float* __restrict__ bias,
                                                 int mode) {
    extern __shared__ char smc[];
    gemm_body(blockIdx.x, x, Wh, nullptr, bias, mode, smc);
}

// ---------------- gather-aggregate (warp/node, 4 HFMA2 chains) ------------
__device__ __forceinline__ void acc_row_h(__half2& a0, __half2& a1,
                                          const __half2* row, int sbits) {
    uint2 u = __ldg((const uint2*)row);
    __half2 s2 = *(__half2*)&sbits;
    a0 = __hfma2(*(__half2*)&u.x, s2, a0);
    a1 = __hfma2(*(__half2*)&u.y, s2, a1);
}

__global__ void __launch_bounds__(256) k_agg() {
    const int tid  = threadIdx.x;
    const int lane = tid & 31;
    const int r = (blockIdx.x * 256 + tid) >> 5;
    if (r >= NNODES) return;

    const int beg = g_off[r], end = g_off[r + 1];
    const float dr = g_dinv[r];

    __half2 a0 = __floats2half2_rn(0.f, 0.f), a1 = a0;   // chain A
    __half2 b0 = a0, b1 = a0;                            // chain B
    {   // self-loop -> chain A
        __half2 h = __floats2half2_rn(dr, dr);
        acc_row_h(a0, a1, &g_hs2[(size_t)r * 64 + lane * 2], *(int*)&h);
    }

    int j = beg;
    for (; j + 8 <= end; j += 8) {
        int2 e[8];
        #pragma unroll
        for (int q = 0; q < 8; q++) e[q] = __ldg(&g_csr2[j + q]);
        #pragma unroll
        for (int q = 0; q < 8; q++) {
            const __half2* row = &g_hs2[(size_t)e[q].x * 64 + lane * 2];
            if (q & 1) acc_row_h(b0, b1, row, e[q].y);
            else       acc_row_h(a0, a1, row, e[q].y);
        }
    }
    for (; j + 4 <= end; j += 4) {
        int2 e[4];
        #pragma unroll
        for (int q = 0; q < 4; q++) e[q] = __ldg(&g_csr2[j + q]);
        #pragma unroll
        for (int q = 0; q < 4; q++) {
            const __half2* row = &g_hs2[(size_t)e[q].x * 64 + lane * 2];
            if (q & 1) acc_row_h(b0, b1, row, e[q].y);
            else       acc_row_h(a0, a1, row, e[q].y);
        }
    }
    for (; j < end; ++j) {
        int2 e = __ldg(&g_csr2[j]);
        acc_row_h(a0, a1, &g_hs2[(size_t)e.x * 64 + lane * 2], e.y);
    }

    a0 = __hadd2(a0, b0);
    a1 = __hadd2(a1, b1);
    uint2 o;
    *(__half2*)&o.x = a0;
    *(__half2*)&o.y = a1;
    *(uint2*)&g_ag2[(size_t)r * 64 + lane * 2] = o;
}

// ---------------- head: relu(ag2*dr+b2) @ Wl^T + bl -> log_softmax --------
#define HEAD_A_BYTES (128 * 256)
#define HEAD_SMEM (HEAD_A_BYTES + 64 * 256)

__global__ void __launch_bounds__(256, 4) k_head(const float* __restrict__ b2,
                                                 const float* __restrict__ Wl,
                                                 const float* __restrict__ bl,
                                                 float* __restrict__ out) {
    extern __shared__ char smc[];
    char* Asb = smc;
    char* Wsb = smc + HEAD_A_BYTES;
    const int tid = threadIdx.x;
    const int r0  = blockIdx.x * 128;

    for (int idx = tid; idx < 384; idx += 256) {
        int c = 40 + (idx >> 4), k8 = idx & 15;
        *(uint4*)(Wsb + sw_off(c, k8)) = make_uint4(0, 0, 0, 0);
    }
    for (int idx = tid; idx < 1280; idx += 256) {
        int flat = idx * 4;
        int c = flat >> 7, k = flat & 127;
        float4 w = *(const float4*)&Wl[c * 128 + k];
        uint2 u;
        *(__half2*)&u.x = __floats2half2_rn(w.x, w.y);
        *(__half2*)&u.y = __floats2half2_rn(w.z, w.w);
        *(uint2*)(Wsb + sw_off(c, k >> 3) + ((k & 7) << 1)) = u;
    }
    #pragma unroll
    for (int j = 0; j < 16; j++) {
        int flat = (tid + j * 256) * 4;
        int rl = flat >> 7, k = flat & 127;
        int r = r0 + rl;
        float4 v = make_float4(0.f, 0.f, 0.f, 0.f);
        if (r < NNODES) {
            uint2 u = *(const uint2*)&g_ag2[(size_t)r * 64 + (k >> 1)];
            float2 a0 = __half22float2(*(const __half2*)&u.x);
            float2 a1 = __half22float2(*(const __half2*)&u.y);
            float4 b = *(const float4*)&b2[k];
            float di = g_dinv[r];
            v.x = fmaxf(fmaf(a0.x, di, b.x), 0.f);
            v.y = fmaxf(fmaf(a0.y, di, b.y), 0.f);
            v.z = fmaxf(fmaf(a1.x, di, b.z), 0.f);
            v.w = fmaxf(fmaf(a1.y, di, b.w), 0.f);
        }
        uint2 u;
        *(__half2*)&u.x = __floats2half2_rn(v.x, v.y);
        *(__half2*)&u.y = __floats2half2_rn(v.z, v.w);
        *(uint2*)(Asb + sw_off(rl, k >> 3) + ((k & 7) << 1)) = u;
    }
    __syncthreads();

    const int warp = tid >> 5, lane = tid & 31;
    const int m0 = warp * 16;
    const int gid = lane >> 2, tig = lane & 3;

    float acc[8][4];
    #pragma unroll
    for (int t = 0; t < 8; t++)
        #pragma unroll
        for (int q = 0; q < 4; q++) acc[t][q] = 0.f;

    unsigned aSm = (unsigned)__cvta_generic_to_shared(Asb);
    unsigned wSm = (unsigned)__cvta_generic_to_shared(Wsb);
    const int aRow = m0 + (lane & 15);
    const int aChA = (lane & 16) ? 1 : 0;
    const int bRow = ((lane & 16) ? 8 : 0) + (lane & 7);
    const int bChA = (lane & 8) ? 1 : 0;

    #pragma unroll
    for (int ks = 0; ks < 8; ks++) {
        unsigned a0, a1, a2, a3;
        unsigned aAddr = aSm + sw_off(aRow, 2 * ks + aChA);
        asm volatile("ldmatrix.sync.aligned.m8n8.x4.shared.b16 {%0,%1,%2,%3},[%4];"
                     : "=r"(a0), "=r"(a1), "=r"(a2), "=r"(a3) : "r"(aAddr));
        #pragma unroll
        for (int tp = 0; tp < 4; tp++) {
            unsigned b0, b1, b2, b3;
            unsigned bAddr = wSm + sw_off(16 * tp + bRow, 2 * ks + bChA);
            asm volatile("ldmatrix.sync.aligned.m8n8.x4.shared.b16 {%0,%1,%2,%3},[%4];"
                         : "=r"(b0), "=r"(b1), "=r"(b2), "=r"(b3) : "r"(bAddr));
            asm volatile("mma.sync.aligned.m16n8k16.row.col.f32.f16.f16.f32 "
                         "{%0,%1,%2,%3},{%4,%5,%6,%7},{%8,%9},{%0,%1,%2,%3};"
                         : "+f"(acc[2 * tp][0]), "+f"(acc[2 * tp][1]),
                           "+f"(acc[2 * tp][2]), "+f"(acc[2 * tp][3])
                         : "r"(a0), "r"(a1), "r"(a2), "r"(a3), "r"(b0), "r"(b1));
            asm volatile("mma.sync.aligned.m16n8k16.row.col.f32.f16.f16.f32 "
                         "{%0,%1,%2,%3},{%4,%5,%6,%7},{%8,%9},{%0,%1,%2,%3};"
                         : "+f"(acc[2 * tp + 1][0]), "+f"(acc[2 * tp + 1][1]),
                           "+f"(acc[2 * tp + 1][2]), "+f"(acc[2 * tp + 1][3])
                         : "r"(a0), "r"(a1), "r"(a2), "r"(a3), "r"(b2), "r"(b3));
        }
    }

    const int r1 = r0 + m0 + gid;
    const int r2 = r1 + 8;

    float lg1[5][2], lg2[5][2];
    float m1 = -1e30f, m2 = -1e30f;
    #pragma unroll
    for (int t = 0; t < 5; t++) {
        int c = 8 * t + 2 * tig;
        float bl0 = __ldg(&bl[c]);
        float bl1 = __ldg(&bl[c + 1]);
        lg1[t][0] = acc[t][0] + bl0; lg1[t][1] = acc[t][1] + bl1;
        lg2[t][0] = acc[t][2] + bl0; lg2[t][1] = acc[t][3] + bl1;
        m1 = fmaxf(m1, fmaxf(lg1[t][0], lg1[t][1]));
        m2 = fmaxf(m2, fmaxf(lg2[t][0], lg2[t][1]));
    }
    #pragma unroll
    for (int s = 1; s <= 2; s <<= 1) {
        m1 = fmaxf(m1, __shfl_xor_sync(0xffffffffu, m1, s));
        m2 = fmaxf(m2, __shfl_xor_sync(0xffffffffu, m2, s));
    }
    float e1 = 0.f, e2 = 0.f;
    #pragma unroll
    for (int t = 0; t < 5; t++) {
        e1 += __expf(lg1[t][0] - m1) + __expf(lg1[t][1] - m1);
        e2 += __expf(lg2[t][0] - m2) + __expf(lg2[t][1] - m2);
    }
    #pragma unroll
    for (int s = 1; s <= 2; s <<= 1) {
        e1 += __shfl_xor_sync(0xffffffffu, e1, s);
        e2 += __shfl_xor_sync(0xffffffffu, e2, s);
    }
    float ls1 = m1 + __logf(e1);
    float ls2 = m2 + __logf(e2);

    #pragma unroll
    for (int t = 0; t < 5; t++) {
        int c = 8 * t + 2 * tig;
        if (r1 < NNODES) {
            float2 o = make_float2(lg1[t][0] - ls1, lg1[t][1] - ls1);
            *(float2*)&out[(size_t)r1 * NCLS + c] = o;
        }
        if (r2 < NNODES) {
            float2 o = make_float2(lg2[t][0] - ls2, lg2[t][1] - ls2);
            *(float2*)&out[(size_t)r2 * NCLS + c] = o;
        }
    }
}

// ---------------- launch ---------------------------------------------------
extern "C" void kernel_launch(void* const* d_in, const int* in_sizes, int n_in,
                              void* d_out, int out_size) {
    const float* x  = (const float*)d_in[0];
    const void*  ei = d_in[1];
    const float* W1 = (const float*)d_in[2];
    const float* b1 = (const float*)d_in[3];
    const float* W2 = (const float*)d_in[4];
    const float* b2 = (const float*)d_in[5];
    const float* Wl = (const float*)d_in[6];
    const float* bl = (const float*)d_in[7];
    float* out = (float*)d_out;

    const long long E = in_sizes[1] / 2;

    cudaFuncSetAttribute(k_gemm, cudaFuncAttributeMaxDynamicSharedMemorySize,
                         GEMM_SMEM);
    cudaFuncSetAttribute(k_cnt_gemm, cudaFuncAttributeMaxDynamicSharedMemorySize,
                         GEMM_SMEM);
    cudaFuncSetAttribute(k_head, cudaFuncAttributeMaxDynamicSharedMemorySize,
                         HEAD_SMEM);

    const int NB_E2   = (int)((E + 511) / 512);
    const int NB_GEMM = (NNODES + 63) / 64;
    const int NB_AGG  = (NNODES * 32 + 255) / 256;
    const int NB_HEAD = (NNODES + 127) / 128;

    __half2* w2h; cudaGetSymbolAddress((void**)&w2h, g_w2h);

    // 1: gemm1 (independent) overlapped with degree count
    k_cnt_gemm<<<NB_GEMM + NB_E2, 256, GEMM_SMEM>>>(x, W1, W2, ei, E, NB_GEMM);
    k_scan<<<NSB, SCAN_B>>>();                                // 2
    k_fill<<<NB_E2, 256>>>(ei, E);                            // 3
    k_agg<<<NB_AGG, 256>>>();                                 // 4
    k_gemm<<<NB_GEMM, 256, GEMM_SMEM>>>(x, w2h, b1, 1);       // 5
    k_agg<<<NB_AGG, 256>>>();                                 // 6
    k_head<<<NB_HEAD, 256, HEAD_SMEM>>>(b2, Wl, bl, out);     // 7
}

// round 17
// speedup vs baseline: 1.7884x; 1.0898x over previous
#include <cuda_runtime.h>
#include <cuda_fp16.h>
#include <math.h>

#define NNODES 50000
#define DIM    128
#define NCLS   40
#define EMAX   600000
#define SCAN_B 1024
#define NSB    ((NNODES + SCAN_B - 1) / SCAN_B)

// ---------------- device scratch ------------------------------------------
__device__ unsigned g_epoch = 0;
__device__ int     g_cnt[NNODES];
__device__ int     g_cur[NNODES];
__device__ int     g_off[NNODES + 1];
__device__ unsigned long long g_state[NSB];
__device__ int2    g_csr2[EMAX];                 // {src, half2(dinv[src]) bits}
__device__ float   g_dinv[NNODES];
__device__ __half2 g_w2h[DIM * DIM / 2];
__device__ __half2 g_hs2[NNODES * (DIM / 2)];    // RAW features h, fp16
__device__ __half2 g_ag2[NNODES * (DIM / 2)];    // aggregation (excl. dinv[dst])

__device__ __forceinline__ int detect64_block(const int* ei) {
    __shared__ int s_is64;
    if (threadIdx.x == 0) {
        int nz = 0;
        #pragma unroll
        for (int j = 0; j < 16; j++) nz += (ei[2 * j + 1] != 0);
        s_is64 = (nz == 0) ? 1 : 0;
    }
    __syncthreads();
    return s_is64;
}

// ---------------- swizzle --------------------------------------------------
__device__ __forceinline__ unsigned sw_off(int r, int chunk) {
    return (unsigned)(r * 256 + ((chunk ^ (r & 7)) << 4));
}

// ---------------- tensor-core GEMM body (swizzled, 64-row tile) -----------
#define A_BYTES (64 * 256)
#define GEMM_SMEM (A_BYTES + 128 * 256)

__device__ void gemm_body(int bx, const float* __restrict__ x,
                          const __half2* __restrict__ Wh,
                          const float* __restrict__ Wf,
                          const float* __restrict__ bias,
                          int mode, char* smc) {
    char* Asb = smc;
    char* Wsb = smc + A_BYTES;
    const int tid = threadIdx.x;
    const int r0  = bx * 64;

    if (Wf) {
        #pragma unroll
        for (int j = 0; j < 16; j++) {
            int flat = (tid + j * 256) * 4;
            int c = flat >> 7, k = flat & 127;
            float4 w = *(const float4*)&Wf[c * 128 + k];
            uint2 u;
            *(__half2*)&u.x = __floats2half2_rn(w.x, w.y);
            *(__half2*)&u.y = __floats2half2_rn(w.z, w.w);
            *(uint2*)(Wsb + sw_off(c, k >> 3) + ((k & 7) << 1)) = u;
        }
    } else {
        #pragma unroll
        for (int j = 0; j < 8; j++) {
            int chunk = tid + j * 256;
            int c  = chunk >> 4;
            int k8 = chunk & 15;
            uint4 u = *(const uint4*)((const char*)Wh + (size_t)chunk * 16);
            *(uint4*)(Wsb + sw_off(c, k8)) = u;
        }
    }
    #pragma unroll
    for (int j = 0; j < 8; j++) {
        int flat = (tid + j * 256) * 4;
        int rl = flat >> 7, k = flat & 127;
        int r = r0 + rl;
        float4 v = make_float4(0.f, 0.f, 0.f, 0.f);
        if (r < NNODES) {
            if (mode == 0) {
                v = *(const float4*)&x[(size_t)r * DIM + k];
            } else {
                uint2 u = *(const uint2*)&g_ag2[(size_t)r * 64 + (k >> 1)];
                float2 a0 = __half22float2(*(const __half2*)&u.x);
                float2 a1 = __half22float2(*(const __half2*)&u.y);
                float4 b = *(const float4*)&bias[k];
                float di = g_dinv[r];
                v.x = fmaxf(fmaf(a0.x, di, b.x), 0.f);
                v.y = fmaxf(fmaf(a0.y, di, b.y), 0.f);
                v.z = fmaxf(fmaf(a1.x, di, b.z), 0.f);
                v.w = fmaxf(fmaf(a1.y, di, b.w), 0.f);
            }
        }
        uint2 u;
        *(__half2*)&u.x = __floats2half2_rn(v.x, v.y);
        *(__half2*)&u.y = __floats2half2_rn(v.z, v.w);
        *(uint2*)(Asb + sw_off(rl, k >> 3) + ((k & 7) << 1)) = u;
    }
    __syncthreads();

    const int warp = tid >> 5, lane = tid & 31;
    const int m0 = (warp >> 1) * 16;
    const int n0 = (warp & 1) * 64;
    const int gid = lane >> 2, tig = lane & 3;

    float acc[8][4];
    #pragma unroll
    for (int t = 0; t < 8; t++)
        #pragma unroll
        for (int q = 0; q < 4; q++) acc[t][q] = 0.f;

    unsigned aSm = (unsigned)__cvta_generic_to_shared(Asb);
    unsigned wSm = (unsigned)__cvta_generic_to_shared(Wsb);
    const int aRow = m0 + (lane & 15);
    const int aChA = (lane & 16) ? 1 : 0;
    const int bRow = ((lane & 16) ? 8 : 0) + (lane & 7);
    const int bChA = (lane & 8) ? 1 : 0;

    #pragma unroll
    for (int ks = 0; ks < 8; ks++) {
        unsigned a0, a1, a2, a3;
        unsigned aAddr = aSm + sw_off(aRow, 2 * ks + aChA);
        asm volatile("ldmatrix.sync.aligned.m8n8.x4.shared.b16 {%0,%1,%2,%3},[%4];"
                     : "=r"(a0), "=r"(a1), "=r"(a2), "=r"(a3) : "r"(aAddr));
        #pragma unroll
        for (int tp = 0; tp < 4; tp++) {
            unsigned b0, b1, b2, b3;
            unsigned bAddr = wSm + sw_off(n0 + 16 * tp + bRow, 2 * ks + bChA);
            asm volatile("ldmatrix.sync.aligned.m8n8.x4.shared.b16 {%0,%1,%2,%3},[%4];"
                         : "=r"(b0), "=r"(b1), "=r"(b2), "=r"(b3) : "r"(bAddr));
            asm volatile("mma.sync.aligned.m16n8k16.row.col.f32.f16.f16.f32 "
                         "{%0,%1,%2,%3},{%4,%5,%6,%7},{%8,%9},{%0,%1,%2,%3};"
                         : "+f"(acc[2 * tp][0]), "+f"(acc[2 * tp][1]),
                           "+f"(acc[2 * tp][2]), "+f"(acc[2 * tp][3])
                         : "r"(a0), "r"(a1), "r"(a2), "r"(a3), "r"(b0), "r"(b1));
            asm volatile("mma.sync.aligned.m16n8k16.row.col.f32.f16.f16.f32 "
                         "{%0,%1,%2,%3},{%4,%5,%6,%7},{%8,%9},{%0,%1,%2,%3};"
                         : "+f"(acc[2 * tp + 1][0]), "+f"(acc[2 * tp + 1][1]),
                           "+f"(acc[2 * tp + 1][2]), "+f"(acc[2 * tp + 1][3])
                         : "r"(a0), "r"(a1), "r"(a2), "r"(a3), "r"(b2), "r"(b3));
        }
    }

    const int r1 = r0 + m0 + gid;
    const int r2 = r1 + 8;
    #pragma unroll
    for (int t = 0; t < 8; t++) {
        int ci = (n0 >> 1) + 4 * t + tig;
        if (r1 < NNODES)
            g_hs2[(size_t)r1 * 64 + ci] = __floats2half2_rn(acc[t][0], acc[t][1]);
        if (r2 < NNODES)
            g_hs2[(size_t)r2 * 64 + ci] = __floats2half2_rn(acc[t][2], acc[t][3]);
    }
}

// ---------------- cnt body (+ W2->fp16, + epoch bump) ---------------------
__device__ __forceinline__ void cnt_body(int bx, const void* ei, long long E,
                                         const float* __restrict__ W2, int is64) {
    int gid = bx * 256 + threadIdx.x;
    if (gid == 0) atomicAdd(&g_epoch, 1u);
    if (gid < DIM * DIM / 2) {
        float2 b = *(const float2*)&W2[2 * gid];
        g_w2h[gid] = __floats2half2_rn(b.x, b.y);
    }
    long long base = (long long)gid * 2;
    if (base >= E) return;
    int d0, d1; bool two = (base + 1 < E);
    if (is64) {
        const long long* pd = (const long long*)ei + E;
        if (two) { longlong2 v = *(const longlong2*)&pd[base]; d0 = (int)v.x; d1 = (int)v.y; }
        else d0 = (int)pd[base];
    } else {
        const int* pd = (const int*)ei + (size_t)E;
        if (two) { int2 v = *(const int2*)&pd[base]; d0 = v.x; d1 = v.y; }
        else d0 = pd[base];
    }
    atomicAdd(&g_cnt[d0], 1);
    if (two) atomicAdd(&g_cnt[d1], 1);
}

__global__ void __launch_bounds__(256, 4) k_cnt_gemm(const float* __restrict__ x,
                                                     const float* __restrict__ W1,
                                                     const float* __restrict__ W2,
                                                     const void* ei, long long E,
                                                     int nGemm) {
    extern __shared__ char smc[];
    if (blockIdx.x < nGemm) {
        gemm_body(blockIdx.x, x, nullptr, W1, nullptr, 0, smc);
    } else {
        const int is64 = detect64_block((const int*)ei);
        cnt_body(blockIdx.x - nGemm, ei, E, W2, is64);
    }
}

// ------- one-pass epoch-tagged lookback scan (+dinv, +cursors, cnt reset) --
__global__ void __launch_bounds__(SCAN_B) k_scan() {
    __shared__ int wsum[32];
    __shared__ int s_run;
    const int tid = threadIdx.x, lane = tid & 31, wid = tid >> 5;
    const int bid = blockIdx.x;
    const int i = bid * SCAN_B + tid;

    const unsigned e = g_epoch;
    const unsigned long long flagP = (unsigned long long)(2u * e + 1u) << 32;
    const unsigned long long flagF = (unsigned long long)(2u * e + 2u) << 32;

    int v = (i < NNODES) ? g_cnt[i] : 0;
    if (i < NNODES) {
        g_dinv[i] = rsqrtf((float)(v + 1));
        g_cnt[i] = 0;
    }

    int incl = v;
    #pragma unroll
    for (int s = 1; s < 32; s <<= 1) {
        int t = __shfl_up_sync(0xffffffffu, incl, s);
        if (lane >= s) incl += t;
    }
    if (lane == 31) wsum[wid] = incl;
    __syncthreads();
    if (wid == 0) {
        int w = wsum[lane];
        int wi = w;
        #pragma unroll
        for (int s = 1; s < 32; s <<= 1) {
            int t = __shfl_up_sync(0xffffffffu, wi, s);
            if (lane >= s) wi += t;
        }
        wsum[lane] = wi - w;
    }
    __syncthreads();
    int excl = incl - v + wsum[wid];

    if (tid == SCAN_B - 1) {
        int total = excl + v;
        long long run = 0;
        if (bid == 0) {
            atomicExch(&g_state[0], flagF | (unsigned)total);
        } else {
            atomicExch(&g_state[bid], flagP | (unsigned)total);
            int p = bid - 1;
            while (true) {
                unsigned long long st = atomicAdd(&g_state[p], 0ULL);
                unsigned long long f = st & 0xFFFFFFFF00000000ULL;
                if (f == flagF) { run += (int)(unsigned)st; break; }
                if (f == flagP) { run += (int)(unsigned)st; --p; continue; }
                __nanosleep(20);
            }
            atomicExch(&g_state[bid], flagF | (unsigned)(run + total));
        }
        s_run = (int)run;
        if (bid == NSB - 1) g_off[NNODES] = (int)run + total;
    }
    __syncthreads();
    if (i < NNODES) {
        int o = excl + s_run;
        g_off[i] = o;
        g_cur[i] = o;
    }
}

// ---------------- CSR fill --------------------------------------------------
__global__ void k_fill(const void* ei, long long E) {
    const int is64 = detect64_block((const int*)ei);
    long long base = ((long long)blockIdx.x * 256 + threadIdx.x) * 2;
    if (base >= E) return;
    int s0, s1, d0, d1; bool two = (base + 1 < E);
    if (is64) {
        const long long* ps = (const long long*)ei;
        const long long* pd = ps + E;
        if (two) {
            longlong2 vs = *(const longlong2*)&ps[base];
            longlong2 vd = *(const longlong2*)&pd[base];
            s0 = (int)vs.x; s1 = (int)vs.y; d0 = (int)vd.x; d1 = (int)vd.y;
        } else { s0 = (int)ps[base]; d0 = (int)pd[base]; }
    } else {
        const int* ps = (const int*)ei;
        const int* pd = ps + (size_t)E;
        if (two) {
            int2 vs = *(const int2*)&ps[base];
            int2 vd = *(const int2*)&pd[base];
            s0 = vs.x; s1 = vs.y; d0 = vd.x; d1 = vd.y;
        } else { s0 = ps[base]; d0 = pd[base]; }
    }
    float f0 = __ldg(&g_dinv[s0]);
    float f1 = two ? __ldg(&g_dinv[s1]) : 0.f;
    __half2 h0 = __floats2half2_rn(f0, f0);
    __half2 h1 = __floats2half2_rn(f1, f1);
    int p0 = atomicAdd(&g_cur[d0], 1);
    int p1 = two ? atomicAdd(&g_cur[d1], 1) : 0;
    g_csr2[p0] = make_int2(s0, *(int*)&h0);
    if (two) g_csr2[p1] = make_int2(s1, *(int*)&h1);
}

__global__ void __launch_bounds__(256, 4) k_gemm(const float* __restrict__ x,
                                                 const __half2* __restrict__ Wh,
                                                 const float* __restrict__ bias,
                                                 int mode) {
    extern __shared__ char smc[];
    gemm_body(blockIdx.x, x, Wh, nullptr, bias, mode, smc);
}

// ------ gather-aggregate: half-warp per edge, LDG.128 row loads ------------
// lanes 0-15 process even edges, 16-31 odd edges; each lane loads one 16B
// chunk (sub) of the 256B feature row. CSR entries fetched as int2 (8B-safe).
__device__ __forceinline__ void acc_pair(uint2& c01, uint2& c23,
                                         int src, int sbits, int sub) {
    const uint4* p = (const uint4*)(g_hs2 + (size_t)src * 64) + sub;
    uint4 u = __ldg(p);
    __half2 s2 = *(__half2*)&sbits;
    *(__half2*)&c01.x = __hfma2(*(__half2*)&u.x, s2, *(__half2*)&c01.x);
    *(__half2*)&c01.y = __hfma2(*(__half2*)&u.y, s2, *(__half2*)&c01.y);
    *(__half2*)&c23.x = __hfma2(*(__half2*)&u.z, s2, *(__half2*)&c23.x);
    *(__half2*)&c23.y = __hfma2(*(__half2*)&u.w, s2, *(__half2*)&c23.y);
}

__global__ void __launch_bounds__(256) k_agg() {
    const int tid  = threadIdx.x;
    const int lane = tid & 31;
    const int half = lane >> 4;       // 0: even edges, 1: odd edges
    const int sub  = lane & 15;       // 16B chunk within the 256B row
    const int r = (blockIdx.x * 256 + tid) >> 5;
    if (r >= NNODES) return;

    const int beg = g_off[r], end = g_off[r + 1];
    const float dr = g_dinv[r];

    uint2 c01 = make_uint2(0u, 0u), c23 = make_uint2(0u, 0u);

    {   // self-loop: half 0 contributes with scale dr, half 1 with zero
        __half2 h = __floats2half2_rn(half ? 0.f : dr, half ? 0.f : dr);
        acc_pair(c01, c23, r, *(int*)&h, sub);
    }

    int j = beg;
    // 8 edges per iteration: each lane loads 4 int2 indices + 4 row LDG.128
    for (; j + 8 <= end; j += 8) {
        int2 e0 = __ldg(&g_csr2[j + 0 + half]);
        int2 e1 = __ldg(&g_csr2[j + 2 + half]);
        int2 e2 = __ldg(&g_csr2[j + 4 + half]);
        int2 e3 = __ldg(&g_csr2[j + 6 + half]);
        acc_pair(c01, c23, e0.x, e0.y, sub);
        acc_pair(c01, c23, e1.x, e1.y, sub);
        acc_pair(c01, c23, e2.x, e2.y, sub);
        acc_pair(c01, c23, e3.x, e3.y, sub);
    }
    for (; j + 2 <= end; j += 2) {
        int2 e = __ldg(&g_csr2[j + half]);
        acc_pair(c01, c23, e.x, e.y, sub);
    }
    if (j < end) {   // single leftover edge: half 1 contributes zero
        int2 e = __ldg(&g_csr2[j]);
        __half2 z = __floats2half2_rn(0.f, 0.f);
        int sb = half ? *(int*)&z : e.y;
        acc_pair(c01, c23, e.x, sb, sub);
    }

    // merge halves (lane L and L+16 hold the same columns)
    unsigned o0 = __shfl_xor_sync(0xffffffffu, c01.x, 16);
    unsigned o1 = __shfl_xor_sync(0xffffffffu, c01.y, 16);
    unsigned o2 = __shfl_xor_sync(0xffffffffu, c23.x, 16);
    unsigned o3 = __shfl_xor_sync(0xffffffffu, c23.y, 16);
    uint4 outv;
    *(__half2*)&outv.x = __hadd2(*(__half2*)&c01.x, *(__half2*)&o0);
    *(__half2*)&outv.y = __hadd2(*(__half2*)&c01.y, *(__half2*)&o1);
    *(__half2*)&outv.z = __hadd2(*(__half2*)&c23.x, *(__half2*)&o2);
    *(__half2*)&outv.w = __hadd2(*(__half2*)&c23.y, *(__half2*)&o3);

    if (half == 0)
        *((uint4*)(g_ag2 + (size_t)r * 64) + sub) = outv;
}

// ---------------- head: relu(ag2*dr+b2) @ Wl^T + bl -> log_softmax --------
#define HEAD_A_BYTES (128 * 256)
#define HEAD_SMEM (HEAD_A_BYTES + 64 * 256)

__global__ void __launch_bounds__(256, 4) k_head(const float* __restrict__ b2,
                                                 const float* __restrict__ Wl,
                                                 const float* __restrict__ bl,
                                                 float* __restrict__ out) {
    extern __shared__ char smc[];
    char* Asb = smc;
    char* Wsb = smc + HEAD_A_BYTES;
    const int tid = threadIdx.x;
    const int r0  = blockIdx.x * 128;

    for (int idx = tid; idx < 384; idx += 256) {
        int c = 40 + (idx >> 4), k8 = idx & 15;
        *(uint4*)(Wsb + sw_off(c, k8)) = make_uint4(0, 0, 0, 0);
    }
    for (int idx = tid; idx < 1280; idx += 256) {
        int flat = idx * 4;
        int c = flat >> 7, k = flat & 127;
        float4 w = *(const float4*)&Wl[c * 128 + k];
        uint2 u;
        *(__half2*)&u.x = __floats2half2_rn(w.x, w.y);
        *(__half2*)&u.y = __floats2half2_rn(w.z, w.w);
        *(uint2*)(Wsb + sw_off(c, k >> 3) + ((k & 7) << 1)) = u;
    }
    #pragma unroll
    for (int j = 0; j < 16; j++) {
        int flat = (tid + j * 256) * 4;
        int rl = flat >> 7, k = flat & 127;
        int r = r0 + rl;
        float4 v = make_float4(0.f, 0.f, 0.f, 0.f);
        if (r < NNODES) {
            uint2 u = *(const uint2*)&g_ag2[(size_t)r * 64 + (k >> 1)];
            float2 a0 = __half22float2(*(const __half2*)&u.x);
            float2 a1 = __half22float2(*(const __half2*)&u.y);
            float4 b = *(const float4*)&b2[k];
            float di = g_dinv[r];
            v.x = fmaxf(fmaf(a0.x, di, b.x), 0.f);
            v.y = fmaxf(fmaf(a0.y, di, b.y), 0.f);
            v.z = fmaxf(fmaf(a1.x, di, b.z), 0.f);
            v.w = fmaxf(fmaf(a1.y, di, b.w), 0.f);
        }
        uint2 u;
        *(__half2*)&u.x = __floats2half2_rn(v.x, v.y);
        *(__half2*)&u.y = __floats2half2_rn(v.z, v.w);
        *(uint2*)(Asb + sw_off(rl, k >> 3) + ((k & 7) << 1)) = u;
    }
    __syncthreads();

    const int warp = tid >> 5, lane = tid & 31;
    const int m0 = warp * 16;
    const int gid = lane >> 2, tig = lane & 3;

    float acc[8][4];
    #pragma unroll
    for (int t = 0; t < 8; t++)
        #pragma unroll
        for (int q = 0; q < 4; q++) acc[t][q] = 0.f;

    unsigned aSm = (unsigned)__cvta_generic_to_shared(Asb);
    unsigned wSm = (unsigned)__cvta_generic_to_shared(Wsb);
    const int aRow = m0 + (lane & 15);
    const int aChA = (lane & 16) ? 1 : 0;
    const int bRow = ((lane & 16) ? 8 : 0) + (lane & 7);
    const int bChA = (lane & 8) ? 1 : 0;

    #pragma unroll
    for (int ks = 0; ks < 8; ks++) {
        unsigned a0, a1, a2, a3;
        unsigned aAddr = aSm + sw_off(aRow, 2 * ks + aChA);
        asm volatile("ldmatrix.sync.aligned.m8n8.x4.shared.b16 {%0,%1,%2,%3},[%4];"
                     : "=r"(a0), "=r"(a1), "=r"(a2), "=r"(a3) : "r"(aAddr));
        #pragma unroll
        for (int tp = 0; tp < 4; tp++) {
            unsigned b0, b1, b2, b3;
            unsigned bAddr = wSm + sw_off(16 * tp + bRow, 2 * ks + bChA);
            asm volatile("ldmatrix.sync.aligned.m8n8.x4.shared.b16 {%0,%1,%2,%3},[%4];"
                         : "=r"(b0), "=r"(b1), "=r"(b2), "=r"(b3) : "r"(bAddr));
            asm volatile("mma.sync.aligned.m16n8k16.row.col.f32.f16.f16.f32 "
                         "{%0,%1,%2,%3},{%4,%5,%6,%7},{%8,%9},{%0,%1,%2,%3};"
                         : "+f"(acc[2 * tp][0]), "+f"(acc[2 * tp][1]),
                           "+f"(acc[2 * tp][2]), "+f"(acc[2 * tp][3])
                         : "r"(a0), "r"(a1), "r"(a2), "r"(a3), "r"(b0), "r"(b1));
            asm volatile("mma.sync.aligned.m16n8k16.row.col.f32.f16.f16.f32 "
                         "{%0,%1,%2,%3},{%4,%5,%6,%7},{%8,%9},{%0,%1,%2,%3};"
                         : "+f"(acc[2 * tp + 1][0]), "+f"(acc[2 * tp + 1][1]),
                           "+f"(acc[2 * tp + 1][2]), "+f"(acc[2 * tp + 1][3])
                         : "r"(a0), "r"(a1), "r"(a2), "r"(a3), "r"(b2), "r"(b3));
        }
    }

    const int r1 = r0 + m0 + gid;
    const int r2 = r1 + 8;

    float lg1[5][2], lg2[5][2];
    float m1 = -1e30f, m2 = -1e30f;
    #pragma unroll
    for (int t = 0; t < 5; t++) {
        int c = 8 * t + 2 * tig;
        float bl0 = __ldg(&bl[c]);
        float bl1 = __ldg(&bl[c + 1]);
        lg1[t][0] = acc[t][0] + bl0; lg1[t][1] = acc[t][1] + bl1;
        lg2[t][0] = acc[t][2] + bl0; lg2[t][1] = acc[t][3] + bl1;
        m1 = fmaxf(m1, fmaxf(lg1[t][0], lg1[t][1]));
        m2 = fmaxf(m2, fmaxf(lg2[t][0], lg2[t][1]));
    }
    #pragma unroll
    for (int s = 1; s <= 2; s <<= 1) {
        m1 = fmaxf(m1, __shfl_xor_sync(0xffffffffu, m1, s));
        m2 = fmaxf(m2, __shfl_xor_sync(0xffffffffu, m2, s));
    }
    float e1 = 0.f, e2 = 0.f;
    #pragma unroll
    for (int t = 0; t < 5; t++) {
        e1 += __expf(lg1[t][0] - m1) + __expf(lg1[t][1] - m1);
        e2 += __expf(lg2[t][0] - m2) + __expf(lg2[t][1] - m2);
    }
    #pragma unroll
    for (int s = 1; s <= 2; s <<= 1) {
        e1 += __shfl_xor_sync(0xffffffffu, e1, s);
        e2 += __shfl_xor_sync(0xffffffffu, e2, s);
    }
    float ls1 = m1 + __logf(e1);
    float ls2 = m2 + __logf(e2);

    #pragma unroll
    for (int t = 0; t < 5; t++) {
        int c = 8 * t + 2 * tig;
        if (r1 < NNODES) {
            float2 o = make_float2(lg1[t][0] - ls1, lg1[t][1] - ls1);
            *(float2*)&out[(size_t)r1 * NCLS + c] = o;
        }
        if (r2 < NNODES) {
            float2 o = make_float2(lg2[t][0] - ls2, lg2[t][1] - ls2);
            *(float2*)&out[(size_t)r2 * NCLS + c] = o;
        }
    }
}

// ---------------- launch ---------------------------------------------------
extern "C" void kernel_launch(void* const* d_in, const int* in_sizes, int n_in,
                              void* d_out, int out_size) {
    const float* x  = (const float*)d_in[0];
    const void*  ei = d_in[1];
    const float* W1 = (const float*)d_in[2];
    const float* b1 = (const float*)d_in[3];
    const float* W2 = (const float*)d_in[4];
    const float* b2 = (const float*)d_in[5];
    const float* Wl = (const float*)d_in[6];
    const float* bl = (const float*)d_in[7];
    float* out = (float*)d_out;

    const long long E = in_sizes[1] / 2;

    cudaFuncSetAttribute(k_gemm, cudaFuncAttributeMaxDynamicSharedMemorySize,
                         GEMM_SMEM);
    cudaFuncSetAttribute(k_cnt_gemm, cudaFuncAttributeMaxDynamicSharedMemorySize,
                         GEMM_SMEM);
    cudaFuncSetAttribute(k_head, cudaFuncAttributeMaxDynamicSharedMemorySize,
                         HEAD_SMEM);

    const int NB_E2   = (int)((E + 511) / 512);
    const int NB_GEMM = (NNODES + 63) / 64;
    const int NB_AGG  = (NNODES * 32 + 255) / 256;
    const int NB_HEAD = (NNODES + 127) / 128;

    __half2* w2h; cudaGetSymbolAddress((void**)&w2h, g_w2h);

    k_cnt_gemm<<<NB_GEMM + NB_E2, 256, GEMM_SMEM>>>(x, W1, W2, ei, E, NB_GEMM);
    k_scan<<<NSB, SCAN_B>>>();
    k_fill<<<NB_E2, 256>>>(ei, E);
    k_agg<<<NB_AGG, 256>>>();
    k_gemm<<<NB_GEMM, 256, GEMM_SMEM>>>(x, w2h, b1, 1);
    k_agg<<<NB_AGG, 256>>>();
    k_head<<<NB_HEAD, 256, HEAD_SMEM>>>(b2, Wl, bl, out);
}